// round 14
// baseline (speedup 1.0000x reference)
#include <cuda_runtime.h>

// Problem constants (fixed by the reference): B=8, C=128, H=W=256, L=3, K=5
#define Bn 8
#define Cn 128

// Scratch (static device globals — no allocation in kernel_launch)
__device__ float g_tag1[(size_t)Bn * Cn * 4 * 64 * 64];   // 67 MB
__device__ float g_tag2[(size_t)Bn * Cn * 4 * 32 * 32];   // 17 MB
__device__ float g_ll1[(size_t)Bn * Cn * 128 * 128];      // 67 MB
__device__ float g_ll2[(size_t)Bn * Cn * 64 * 64];        // 17 MB

// ---------------------------------------------------------------------------
// ll_kernel: compute ll1 = HaarLL(x) and ll2 = HaarLL(ll1) in one streaming
// pass. Register-only, no smem, no syncs. Each thread: 8x8 x -> 4x4 ll1 -> 2x2 ll2.
// Block = 256 threads covers 128x128 of x; 4 blocks per (b,c) plane.
// ---------------------------------------------------------------------------
__global__ __launch_bounds__(256) void ll_kernel(const float* __restrict__ x)
{
    const int tid = threadIdx.x;
    const int tile = blockIdx.x;                 // 0..3
    const int c = blockIdx.y, b = blockIdx.z;
    const int ti = (tile >> 1) * 128, tj = (tile & 1) * 128;
    const int tyy = tid >> 4, txx = tid & 15;
    const int xi = ti + 8 * tyy, xj = tj + 8 * txx;

    const float* xp = x + (size_t)(b * Cn + c) * 65536;
    float* l1 = g_ll1 + (size_t)(b * Cn + c) * 16384;
    float* l2 = g_ll2 + (size_t)(b * Cn + c) * 4096;

    float l1v[4][4];
#pragma unroll
    for (int r = 0; r < 4; ++r) {
        const float* r0 = xp + (size_t)(xi + 2 * r) * 256 + xj;
        const float* r1 = r0 + 256;
        float4 a0 = *(const float4*)r0;
        float4 a1 = *(const float4*)(r0 + 4);
        float4 b0 = *(const float4*)r1;
        float4 b1 = *(const float4*)(r1 + 4);
        l1v[r][0] = 0.5f * (a0.x + a0.y + b0.x + b0.y);
        l1v[r][1] = 0.5f * (a0.z + a0.w + b0.z + b0.w);
        l1v[r][2] = 0.5f * (a1.x + a1.y + b1.x + b1.y);
        l1v[r][3] = 0.5f * (a1.z + a1.w + b1.z + b1.w);
        *(float4*)(l1 + (size_t)(xi / 2 + r) * 128 + xj / 2) =
            make_float4(l1v[r][0], l1v[r][1], l1v[r][2], l1v[r][3]);
    }
#pragma unroll
    for (int r = 0; r < 2; ++r) {
        float2 v = make_float2(
            0.5f * (l1v[2 * r][0] + l1v[2 * r][1] + l1v[2 * r + 1][0] + l1v[2 * r + 1][1]),
            0.5f * (l1v[2 * r][2] + l1v[2 * r][3] + l1v[2 * r + 1][2] + l1v[2 * r + 1][3]));
        *(float2*)(l2 + (size_t)(xi / 4 + r) * 64 + xj / 4) = v;
    }
}

// ---------------------------------------------------------------------------
// Forward kernel for levels 1 and 2: Haar analysis of ll{1,2} + depthwise 5x5
// conv (SAME, x wscale) -> tag{1,2}. No LL write (ll_kernel produced both).
// ---------------------------------------------------------------------------
template <int LEVEL>
__global__ __launch_bounds__(256) void fwd_kernel(
    const float* __restrict__ wconv_all,    // (L, 4C, 1, 5, 5)
    const float* __restrict__ wscale_all)   // (L, 1, 4C, 1, 1)
{
    constexpr int HC = (LEVEL == 1) ? 64 : 32;

    __shared__ __align__(16) float sc[4][36][40];
    __shared__ float sw[4][25];
    __shared__ float ss[4];

    const int tid = threadIdx.x;
    const int TPR = HC / 32;
    const int tx = blockIdx.x % TPR, ty = blockIdx.x / TPR;
    const int i0 = ty * 32, j0 = tx * 32;
    const int c = blockIdx.y, b = blockIdx.z;

    const float* wconv  = wconv_all  + (size_t)LEVEL * (4 * Cn) * 25;
    const float* wscale = wscale_all + (size_t)LEVEL * (4 * Cn);

    if (tid < 100) sw[tid / 25][tid % 25] = wconv[(c * 4 + tid / 25) * 25 + tid % 25];
    else if (tid < 104) ss[tid - 100] = wscale[c * 4 + (tid - 100)];

    const float* inp = (LEVEL == 1)
        ? (g_ll1 + (size_t)(b * Cn + c) * (4 * HC * HC))
        : (g_ll2 + (size_t)(b * Cn + c) * (4 * HC * HC));
    float* tag = (LEVEL == 1) ? g_tag1 : g_tag2;

    for (int idx = tid; idx < 36 * 36; idx += 256) {
        int ci = idx / 36, cj = idx % 36;
        int gi = i0 - 2 + ci, gj = j0 - 2 + cj;
        float x00 = 0.f, x01 = 0.f, x10 = 0.f, x11 = 0.f;
        if ((unsigned)gi < (unsigned)HC && (unsigned)gj < (unsigned)HC) {
            const float* p = inp + (size_t)(2 * gi) * (2 * HC) + 2 * gj;
            float2 a  = *(const float2*)p;
            float2 bb = *(const float2*)(p + 2 * HC);
            x00 = a.x; x01 = a.y; x10 = bb.x; x11 = bb.y;
        }
        float pa = x00 + x01, pb = x10 + x11;
        float pc = x00 - x01, pd = x10 - x11;
        sc[0][ci][cj] = 0.5f * (pa + pb);
        sc[1][ci][cj] = 0.5f * (pa - pb);
        sc[2][ci][cj] = 0.5f * (pc + pd);
        sc[3][ci][cj] = 0.5f * (pc - pd);
    }
    __syncthreads();

    const int f = tid >> 6;
    const int u = tid & 63;
    const int bi = u >> 3, bj = u & 7;

    float wreg[25];
#pragma unroll
    for (int k = 0; k < 25; ++k) wreg[k] = sw[f][k];

    float acc[4][4];
#pragma unroll
    for (int a = 0; a < 4; ++a)
#pragma unroll
        for (int d = 0; d < 4; ++d) acc[a][d] = 0.f;

#pragma unroll
    for (int r = 0; r < 8; ++r) {
        float rv[8];
        float4 v0 = *(const float4*)&sc[f][4 * bi + r][4 * bj];
        float4 v1 = *(const float4*)&sc[f][4 * bi + r][4 * bj + 4];
        rv[0] = v0.x; rv[1] = v0.y; rv[2] = v0.z; rv[3] = v0.w;
        rv[4] = v1.x; rv[5] = v1.y; rv[6] = v1.z; rv[7] = v1.w;
#pragma unroll
        for (int di = 0; di < 5; ++di) {
            int oi = r - di;
            if (oi >= 0 && oi < 4) {
#pragma unroll
                for (int dj = 0; dj < 5; ++dj) {
                    float wv = wreg[di * 5 + dj];
#pragma unroll
                    for (int cj = 0; cj < 4; ++cj)
                        acc[oi][cj] = fmaf(rv[cj + dj], wv, acc[oi][cj]);
                }
            }
        }
    }

    float s = ss[f];
    float* tp = tag + ((size_t)((b * Cn + c) * 4 + f)) * HC * HC;
#pragma unroll
    for (int oi = 0; oi < 4; ++oi) {
        float4 v = make_float4(acc[oi][0] * s, acc[oi][1] * s,
                               acc[oi][2] * s, acc[oi][3] * s);
        *(float4*)&tp[(size_t)(i0 + 4 * bi + oi) * HC + (j0 + 4 * bj)] = v;
    }
}

// ---------------------------------------------------------------------------
// final_kernel: per 32x32 output tile —
//   - load 40x40 x tile (float4, all-or-nothing bounds)
//   - stage tag1 (8x8x4) and tag2 (4x4x4) into smem (coalesced)
//   - compute level-0 Haar coefficients (20x20x4) in smem
//   - depthwise 5x5 conv -> tag0 (16x16x4) in smem  [tag0 never hits DRAM]
//   - base 5x5 conv on x + fused 3-level inverse Haar -> out
// ---------------------------------------------------------------------------
__global__ __launch_bounds__(256) void final_kernel(
    const float* __restrict__ x,
    const float* __restrict__ base_w,      // (C,1,5,5)
    const float* __restrict__ base_b,      // (C,)
    const float* __restrict__ base_scale,  // (1,C,1,1)
    const float* __restrict__ wconv_all,   // (L,4C,1,5,5): level 0 at offset 0
    const float* __restrict__ wscale_all,  // (L,1,4C,1,1)
    float* __restrict__ out)
{
    __shared__ __align__(16) float sx[40][40];
    __shared__ __align__(16) float scf[4][20][24];
    __shared__ __align__(16) float st0[4][16][20];
    __shared__ float st1[4][8][9];
    __shared__ float st2[4][4][5];
    __shared__ float swt[25];
    __shared__ float sw0[4][25];
    __shared__ float ss0[4];

    const int tid = threadIdx.x;
    const int tx = blockIdx.x & 7, ty = blockIdx.x >> 3;
    const int p0 = ty * 32, q0 = tx * 32;
    const int c = blockIdx.y, b = blockIdx.z;

    // Stage weights
    if (tid < 25) {
        swt[tid] = base_w[c * 25 + tid];
    } else if (tid >= 32 && tid < 132) {
        int k = tid - 32;
        sw0[k / 25][k % 25] = wconv_all[(c * 4 + k / 25) * 25 + k % 25];
    } else if (tid >= 160 && tid < 164) {
        ss0[tid - 160] = wscale_all[c * 4 + (tid - 160)];
    }

    // Stage tag1 / tag2 (cooperative, coalesced)
    const size_t bcc = (size_t)(b * Cn + c) * 4;
    const float* t1 = g_tag1 + bcc * 4096;
    const float* t2 = g_tag2 + bcc * 1024;
    const int I1 = p0 >> 2, J1 = q0 >> 2;
    const int I2 = p0 >> 3, J2 = q0 >> 3;
    {
        int f = tid >> 6, r = (tid >> 3) & 7, co = tid & 7;
        st1[f][r][co] = __ldg(t1 + f * 4096 + (I1 + r) * 64 + (J1 + co));
    }
    if (tid < 64) {
        int f = tid >> 4, r = (tid >> 2) & 3, co = tid & 3;
        st2[f][r][co] = __ldg(t2 + f * 1024 + (I2 + r) * 32 + (J2 + co));
    }

    // Stage x tile: rows/cols [p0-4, p0+35] x [q0-4, q0+35], float4 granules.
    // Each float4 is fully in-bounds or fully out (q0-4 ≡ 4 mod 8, granule aligned).
    const float* xp = x + (size_t)(b * Cn + c) * 65536;
    for (int idx = tid; idx < 400; idx += 256) {
        int r = idx / 10, c4 = idx % 10;
        int gi = p0 - 4 + r;
        int gj = q0 - 4 + 4 * c4;
        float4 v = make_float4(0.f, 0.f, 0.f, 0.f);
        if ((unsigned)gi < 256u && (unsigned)gj < 256u)
            v = *(const float4*)(xp + (size_t)gi * 256 + gj);
        *(float4*)&sx[r][4 * c4] = v;
    }
    __syncthreads();

    // Level-0 Haar coefficients (20x20 per subband, conv halo 2 included;
    // out-of-image coefficients are exactly 0 because sx halo is 0)
    for (int idx = tid; idx < 400; idx += 256) {
        int ci = idx / 20, cj = idx % 20;
        float2 a  = *(const float2*)&sx[2 * ci][2 * cj];
        float2 bb = *(const float2*)&sx[2 * ci + 1][2 * cj];
        float pa = a.x + a.y, pb = bb.x + bb.y;
        float pc = a.x - a.y, pd = bb.x - bb.y;
        scf[0][ci][cj] = 0.5f * (pa + pb);
        scf[1][ci][cj] = 0.5f * (pa - pb);
        scf[2][ci][cj] = 0.5f * (pc + pd);
        scf[3][ci][cj] = 0.5f * (pc - pd);
    }
    __syncthreads();

    // tag0 = wscale0 * dwconv5x5(coeffs): subband f handled by warp-group f,
    // each thread 1x4 outputs (row bi, cols 4*(u&3) ..)
    {
        int f = tid >> 6, u = tid & 63;
        int bi = u >> 2, bj4 = (u & 3) * 4;
        float wr[25];
#pragma unroll
        for (int k = 0; k < 25; ++k) wr[k] = sw0[f][k];
        float a0 = 0.f, a1 = 0.f, a2 = 0.f, a3 = 0.f;
#pragma unroll
        for (int di = 0; di < 5; ++di) {
            float rv[8];
            float4 v0 = *(const float4*)&scf[f][bi + di][bj4];
            float4 v1 = *(const float4*)&scf[f][bi + di][bj4 + 4];
            rv[0] = v0.x; rv[1] = v0.y; rv[2] = v0.z; rv[3] = v0.w;
            rv[4] = v1.x; rv[5] = v1.y; rv[6] = v1.z; rv[7] = v1.w;
#pragma unroll
            for (int dj = 0; dj < 5; ++dj) {
                float wv = wr[di * 5 + dj];
                a0 = fmaf(rv[dj],     wv, a0);
                a1 = fmaf(rv[dj + 1], wv, a1);
                a2 = fmaf(rv[dj + 2], wv, a2);
                a3 = fmaf(rv[dj + 3], wv, a3);
            }
        }
        float s = ss0[f];
        *(float4*)&st0[f][bi][bj4] = make_float4(a0 * s, a1 * s, a2 * s, a3 * s);
    }
    __syncthreads();

    // Final phase: base 5x5 conv (2x2 outputs) + fused 3-level inverse Haar
    const int bi2 = tid >> 4, bj2 = tid & 15;

    float a00 = 0.f, a01 = 0.f, a10 = 0.f, a11 = 0.f;
#pragma unroll
    for (int r = 0; r < 7; ++r) {
        float rv[8];
        const float* rowp = &sx[2 * bi2 + 2 + r][2 * bj2 + 2];
#pragma unroll
        for (int k = 0; k < 4; ++k) {
            float2 t = *(const float2*)(rowp + 2 * k);
            rv[2 * k] = t.x; rv[2 * k + 1] = t.y;
        }
        {
            int di = r;           // oi = 0
            if (di < 5) {
#pragma unroll
                for (int dj = 0; dj < 5; ++dj) {
                    float wv = swt[di * 5 + dj];
                    a00 = fmaf(rv[dj],     wv, a00);
                    a01 = fmaf(rv[dj + 1], wv, a01);
                }
            }
        }
        {
            int di = r - 1;       // oi = 1
            if (di >= 0 && di < 5) {
#pragma unroll
                for (int dj = 0; dj < 5; ++dj) {
                    float wv = swt[di * 5 + dj];
                    a10 = fmaf(rv[dj],     wv, a10);
                    a11 = fmaf(rv[dj + 1], wv, a11);
                }
            }
        }
    }

    // Inverse Haar: levels 2 -> 1 -> 0 (all values from smem)
    float u0 = st0[0][bi2][bj2], u1 = st0[1][bi2][bj2];
    float u2 = st0[2][bi2][bj2], u3 = st0[3][bi2][bj2];
    int r1 = bi2 >> 1, c1 = bj2 >> 1;
    float v0 = st1[0][r1][c1], v1 = st1[1][r1][c1];
    float v2 = st1[2][r1][c1], v3 = st1[3][r1][c1];
    int r2 = bi2 >> 2, c2 = bj2 >> 2;
    float w0 = st2[0][r2][c2], w1 = st2[1][r2][c2];
    float w2 = st2[2][r2][c2], w3 = st2[3][r2][c2];

    float sA = (r1 & 1) ? -1.f : 1.f;
    float sB = (c1 & 1) ? -1.f : 1.f;
    float nll2 = 0.5f * (w0 + sA * w1 + sB * w2 + sA * sB * w3);

    float sC = (bi2 & 1) ? -1.f : 1.f;
    float sD = (bj2 & 1) ? -1.f : 1.f;
    float nll1 = 0.5f * ((v0 + nll2) + sC * v1 + sD * v2 + sC * sD * v3);

    float y0 = u0 + nll1;
    float r00 = 0.5f * (y0 + u1 + u2 + u3);
    float r01 = 0.5f * (y0 + u1 - u2 - u3);
    float r10 = 0.5f * (y0 - u1 + u2 - u3);
    float r11 = 0.5f * (y0 - u1 - u2 + u3);

    float bsc = __ldg(base_scale + c);
    float bbv = __ldg(base_b + c);

    float* op = out + (size_t)(b * Cn + c) * 65536
                    + (size_t)(p0 + 2 * bi2) * 256 + (q0 + 2 * bj2);
    *(float2*)op         = make_float2(bsc * (a00 + bbv) + r00, bsc * (a01 + bbv) + r01);
    *(float2*)(op + 256) = make_float2(bsc * (a10 + bbv) + r10, bsc * (a11 + bbv) + r11);
}

// ---------------------------------------------------------------------------
// kernel_launch: 4 launches, one stream, graph-capturable, allocation-free.
// Input order: x, wt_filter, iwt_filter, base_w, base_b, base_scale,
//              wconv_w, wscale  (Haar filters are fixed constants, inlined)
// ---------------------------------------------------------------------------
extern "C" void kernel_launch(void* const* d_in, const int* in_sizes, int n_in,
                              void* d_out, int out_size) {
    (void)in_sizes; (void)n_in; (void)out_size;
    const float* x          = (const float*)d_in[0];
    const float* base_w     = (const float*)d_in[3];
    const float* base_b     = (const float*)d_in[4];
    const float* base_scale = (const float*)d_in[5];
    const float* wconv_w    = (const float*)d_in[6];
    const float* wscale     = (const float*)d_in[7];
    float* out = (float*)d_out;

    ll_kernel<<<dim3(4, Cn, Bn), 256>>>(x);
    fwd_kernel<1><<<dim3(4, Cn, Bn), 256>>>(wconv_w, wscale);
    fwd_kernel<2><<<dim3(1, Cn, Bn), 256>>>(wconv_w, wscale);
    final_kernel<<<dim3(64, Cn, Bn), 256>>>(x, base_w, base_b, base_scale,
                                            wconv_w, wscale, out);
}

// round 15
// speedup vs baseline: 1.0010x; 1.0010x over previous
#include <cuda_runtime.h>

// Problem constants (fixed by the reference): B=8, C=128, H=W=256, L=3, K=5
#define Bn 8
#define Cn 128

// Scratch (static device globals — no allocation in kernel_launch)
__device__ float g_tag1[(size_t)Bn * Cn * 4 * 64 * 64];   // 67 MB
__device__ float g_tag2[(size_t)Bn * Cn * 4 * 32 * 32];   // 17 MB
__device__ float g_ll1[(size_t)Bn * Cn * 128 * 128];      // 67 MB
__device__ float g_ll2[(size_t)Bn * Cn * 64 * 64];        // 17 MB

// ---------------------------------------------------------------------------
// ll_kernel: compute ll1 = HaarLL(x) and ll2 = HaarLL(ll1) in one streaming
// pass. Register-only, no smem, no syncs. Each thread: 8x8 x -> 4x4 ll1 -> 2x2 ll2.
// Block = 256 threads covers 128x128 of x; 4 blocks per (b,c) plane.
// ---------------------------------------------------------------------------
__global__ __launch_bounds__(256) void ll_kernel(const float* __restrict__ x)
{
    const int tid = threadIdx.x;
    const int tile = blockIdx.x;                 // 0..3
    const int c = blockIdx.y, b = blockIdx.z;
    const int ti = (tile >> 1) * 128, tj = (tile & 1) * 128;
    const int tyy = tid >> 4, txx = tid & 15;
    const int xi = ti + 8 * tyy, xj = tj + 8 * txx;

    const float* xp = x + (size_t)(b * Cn + c) * 65536;
    float* l1 = g_ll1 + (size_t)(b * Cn + c) * 16384;
    float* l2 = g_ll2 + (size_t)(b * Cn + c) * 4096;

    float l1v[4][4];
#pragma unroll
    for (int r = 0; r < 4; ++r) {
        const float* r0 = xp + (size_t)(xi + 2 * r) * 256 + xj;
        const float* r1 = r0 + 256;
        float4 a0 = *(const float4*)r0;
        float4 a1 = *(const float4*)(r0 + 4);
        float4 b0 = *(const float4*)r1;
        float4 b1 = *(const float4*)(r1 + 4);
        l1v[r][0] = 0.5f * (a0.x + a0.y + b0.x + b0.y);
        l1v[r][1] = 0.5f * (a0.z + a0.w + b0.z + b0.w);
        l1v[r][2] = 0.5f * (a1.x + a1.y + b1.x + b1.y);
        l1v[r][3] = 0.5f * (a1.z + a1.w + b1.z + b1.w);
        *(float4*)(l1 + (size_t)(xi / 2 + r) * 128 + xj / 2) =
            make_float4(l1v[r][0], l1v[r][1], l1v[r][2], l1v[r][3]);
    }
#pragma unroll
    for (int r = 0; r < 2; ++r) {
        float2 v = make_float2(
            0.5f * (l1v[2 * r][0] + l1v[2 * r][1] + l1v[2 * r + 1][0] + l1v[2 * r + 1][1]),
            0.5f * (l1v[2 * r][2] + l1v[2 * r][3] + l1v[2 * r + 1][2] + l1v[2 * r + 1][3]));
        *(float2*)(l2 + (size_t)(xi / 4 + r) * 64 + xj / 4) = v;
    }
}

// ---------------------------------------------------------------------------
// Forward kernel for levels 1 and 2: Haar analysis of ll{1,2} + depthwise 5x5
// conv (SAME, x wscale) -> tag{1,2}. No LL write (ll_kernel produced both).
// ---------------------------------------------------------------------------
template <int LEVEL>
__global__ __launch_bounds__(256) void fwd_kernel(
    const float* __restrict__ wconv_all,    // (L, 4C, 1, 5, 5)
    const float* __restrict__ wscale_all)   // (L, 1, 4C, 1, 1)
{
    constexpr int HC = (LEVEL == 1) ? 64 : 32;

    __shared__ __align__(16) float sc[4][36][40];
    __shared__ float sw[4][25];
    __shared__ float ss[4];

    const int tid = threadIdx.x;
    const int TPR = HC / 32;
    const int tx = blockIdx.x % TPR, ty = blockIdx.x / TPR;
    const int i0 = ty * 32, j0 = tx * 32;
    const int c = blockIdx.y, b = blockIdx.z;

    const float* wconv  = wconv_all  + (size_t)LEVEL * (4 * Cn) * 25;
    const float* wscale = wscale_all + (size_t)LEVEL * (4 * Cn);

    if (tid < 100) sw[tid / 25][tid % 25] = wconv[(c * 4 + tid / 25) * 25 + tid % 25];
    else if (tid < 104) ss[tid - 100] = wscale[c * 4 + (tid - 100)];

    const float* inp = (LEVEL == 1)
        ? (g_ll1 + (size_t)(b * Cn + c) * (4 * HC * HC))
        : (g_ll2 + (size_t)(b * Cn + c) * (4 * HC * HC));
    float* tag = (LEVEL == 1) ? g_tag1 : g_tag2;

    for (int idx = tid; idx < 36 * 36; idx += 256) {
        int ci = idx / 36, cj = idx % 36;
        int gi = i0 - 2 + ci, gj = j0 - 2 + cj;
        float x00 = 0.f, x01 = 0.f, x10 = 0.f, x11 = 0.f;
        if ((unsigned)gi < (unsigned)HC && (unsigned)gj < (unsigned)HC) {
            const float* p = inp + (size_t)(2 * gi) * (2 * HC) + 2 * gj;
            float2 a  = *(const float2*)p;
            float2 bb = *(const float2*)(p + 2 * HC);
            x00 = a.x; x01 = a.y; x10 = bb.x; x11 = bb.y;
        }
        float pa = x00 + x01, pb = x10 + x11;
        float pc = x00 - x01, pd = x10 - x11;
        sc[0][ci][cj] = 0.5f * (pa + pb);
        sc[1][ci][cj] = 0.5f * (pa - pb);
        sc[2][ci][cj] = 0.5f * (pc + pd);
        sc[3][ci][cj] = 0.5f * (pc - pd);
    }
    __syncthreads();

    const int f = tid >> 6;
    const int u = tid & 63;
    const int bi = u >> 3, bj = u & 7;

    float wreg[25];
#pragma unroll
    for (int k = 0; k < 25; ++k) wreg[k] = sw[f][k];

    float acc[4][4];
#pragma unroll
    for (int a = 0; a < 4; ++a)
#pragma unroll
        for (int d = 0; d < 4; ++d) acc[a][d] = 0.f;

#pragma unroll
    for (int r = 0; r < 8; ++r) {
        float rv[8];
        float4 v0 = *(const float4*)&sc[f][4 * bi + r][4 * bj];
        float4 v1 = *(const float4*)&sc[f][4 * bi + r][4 * bj + 4];
        rv[0] = v0.x; rv[1] = v0.y; rv[2] = v0.z; rv[3] = v0.w;
        rv[4] = v1.x; rv[5] = v1.y; rv[6] = v1.z; rv[7] = v1.w;
#pragma unroll
        for (int di = 0; di < 5; ++di) {
            int oi = r - di;
            if (oi >= 0 && oi < 4) {
#pragma unroll
                for (int dj = 0; dj < 5; ++dj) {
                    float wv = wreg[di * 5 + dj];
#pragma unroll
                    for (int cj = 0; cj < 4; ++cj)
                        acc[oi][cj] = fmaf(rv[cj + dj], wv, acc[oi][cj]);
                }
            }
        }
    }

    float s = ss[f];
    float* tp = tag + ((size_t)((b * Cn + c) * 4 + f)) * HC * HC;
#pragma unroll
    for (int oi = 0; oi < 4; ++oi) {
        float4 v = make_float4(acc[oi][0] * s, acc[oi][1] * s,
                               acc[oi][2] * s, acc[oi][3] * s);
        *(float4*)&tp[(size_t)(i0 + 4 * bi + oi) * HC + (j0 + 4 * bj)] = v;
    }
}

// ---------------------------------------------------------------------------
// final_kernel: per 32x32 output tile —
//   - load 40x40 x tile (float4, all-or-nothing bounds)
//   - stage tag1 (8x8x4) and tag2 (4x4x4) into smem (coalesced)
//   - compute level-0 Haar coefficients (20x20x4) in smem
//   - depthwise 5x5 conv -> tag0 (16x16x4) in smem  [tag0 never hits DRAM]
//   - base 5x5 conv on x + fused 3-level inverse Haar -> out
// ---------------------------------------------------------------------------
__global__ __launch_bounds__(256) void final_kernel(
    const float* __restrict__ x,
    const float* __restrict__ base_w,      // (C,1,5,5)
    const float* __restrict__ base_b,      // (C,)
    const float* __restrict__ base_scale,  // (1,C,1,1)
    const float* __restrict__ wconv_all,   // (L,4C,1,5,5): level 0 at offset 0
    const float* __restrict__ wscale_all,  // (L,1,4C,1,1)
    float* __restrict__ out)
{
    __shared__ __align__(16) float sx[40][40];
    __shared__ __align__(16) float scf[4][20][24];
    __shared__ __align__(16) float st0[4][16][20];
    __shared__ float st1[4][8][9];
    __shared__ float st2[4][4][5];
    __shared__ float swt[25];
    __shared__ float sw0[4][25];
    __shared__ float ss0[4];

    const int tid = threadIdx.x;
    const int tx = blockIdx.x & 7, ty = blockIdx.x >> 3;
    const int p0 = ty * 32, q0 = tx * 32;
    const int c = blockIdx.y, b = blockIdx.z;

    // Stage weights
    if (tid < 25) {
        swt[tid] = base_w[c * 25 + tid];
    } else if (tid >= 32 && tid < 132) {
        int k = tid - 32;
        sw0[k / 25][k % 25] = wconv_all[(c * 4 + k / 25) * 25 + k % 25];
    } else if (tid >= 160 && tid < 164) {
        ss0[tid - 160] = wscale_all[c * 4 + (tid - 160)];
    }

    // Stage tag1 / tag2 (cooperative, coalesced)
    const size_t bcc = (size_t)(b * Cn + c) * 4;
    const float* t1 = g_tag1 + bcc * 4096;
    const float* t2 = g_tag2 + bcc * 1024;
    const int I1 = p0 >> 2, J1 = q0 >> 2;
    const int I2 = p0 >> 3, J2 = q0 >> 3;
    {
        int f = tid >> 6, r = (tid >> 3) & 7, co = tid & 7;
        st1[f][r][co] = __ldg(t1 + f * 4096 + (I1 + r) * 64 + (J1 + co));
    }
    if (tid < 64) {
        int f = tid >> 4, r = (tid >> 2) & 3, co = tid & 3;
        st2[f][r][co] = __ldg(t2 + f * 1024 + (I2 + r) * 32 + (J2 + co));
    }

    // Stage x tile: rows/cols [p0-4, p0+35] x [q0-4, q0+35], float4 granules.
    // Each float4 is fully in-bounds or fully out (q0-4 ≡ 4 mod 8, granule aligned).
    const float* xp = x + (size_t)(b * Cn + c) * 65536;
    for (int idx = tid; idx < 400; idx += 256) {
        int r = idx / 10, c4 = idx % 10;
        int gi = p0 - 4 + r;
        int gj = q0 - 4 + 4 * c4;
        float4 v = make_float4(0.f, 0.f, 0.f, 0.f);
        if ((unsigned)gi < 256u && (unsigned)gj < 256u)
            v = *(const float4*)(xp + (size_t)gi * 256 + gj);
        *(float4*)&sx[r][4 * c4] = v;
    }
    __syncthreads();

    // Level-0 Haar coefficients (20x20 per subband, conv halo 2 included;
    // out-of-image coefficients are exactly 0 because sx halo is 0)
    for (int idx = tid; idx < 400; idx += 256) {
        int ci = idx / 20, cj = idx % 20;
        float2 a  = *(const float2*)&sx[2 * ci][2 * cj];
        float2 bb = *(const float2*)&sx[2 * ci + 1][2 * cj];
        float pa = a.x + a.y, pb = bb.x + bb.y;
        float pc = a.x - a.y, pd = bb.x - bb.y;
        scf[0][ci][cj] = 0.5f * (pa + pb);
        scf[1][ci][cj] = 0.5f * (pa - pb);
        scf[2][ci][cj] = 0.5f * (pc + pd);
        scf[3][ci][cj] = 0.5f * (pc - pd);
    }
    __syncthreads();

    // tag0 = wscale0 * dwconv5x5(coeffs): subband f handled by warp-group f,
    // each thread 1x4 outputs (row bi, cols 4*(u&3) ..)
    {
        int f = tid >> 6, u = tid & 63;
        int bi = u >> 2, bj4 = (u & 3) * 4;
        float wr[25];
#pragma unroll
        for (int k = 0; k < 25; ++k) wr[k] = sw0[f][k];
        float a0 = 0.f, a1 = 0.f, a2 = 0.f, a3 = 0.f;
#pragma unroll
        for (int di = 0; di < 5; ++di) {
            float rv[8];
            float4 v0 = *(const float4*)&scf[f][bi + di][bj4];
            float4 v1 = *(const float4*)&scf[f][bi + di][bj4 + 4];
            rv[0] = v0.x; rv[1] = v0.y; rv[2] = v0.z; rv[3] = v0.w;
            rv[4] = v1.x; rv[5] = v1.y; rv[6] = v1.z; rv[7] = v1.w;
#pragma unroll
            for (int dj = 0; dj < 5; ++dj) {
                float wv = wr[di * 5 + dj];
                a0 = fmaf(rv[dj],     wv, a0);
                a1 = fmaf(rv[dj + 1], wv, a1);
                a2 = fmaf(rv[dj + 2], wv, a2);
                a3 = fmaf(rv[dj + 3], wv, a3);
            }
        }
        float s = ss0[f];
        *(float4*)&st0[f][bi][bj4] = make_float4(a0 * s, a1 * s, a2 * s, a3 * s);
    }
    __syncthreads();

    // Final phase: base 5x5 conv (2x2 outputs) + fused 3-level inverse Haar
    const int bi2 = tid >> 4, bj2 = tid & 15;

    float a00 = 0.f, a01 = 0.f, a10 = 0.f, a11 = 0.f;
#pragma unroll
    for (int r = 0; r < 7; ++r) {
        float rv[8];
        const float* rowp = &sx[2 * bi2 + 2 + r][2 * bj2 + 2];
#pragma unroll
        for (int k = 0; k < 4; ++k) {
            float2 t = *(const float2*)(rowp + 2 * k);
            rv[2 * k] = t.x; rv[2 * k + 1] = t.y;
        }
        {
            int di = r;           // oi = 0
            if (di < 5) {
#pragma unroll
                for (int dj = 0; dj < 5; ++dj) {
                    float wv = swt[di * 5 + dj];
                    a00 = fmaf(rv[dj],     wv, a00);
                    a01 = fmaf(rv[dj + 1], wv, a01);
                }
            }
        }
        {
            int di = r - 1;       // oi = 1
            if (di >= 0 && di < 5) {
#pragma unroll
                for (int dj = 0; dj < 5; ++dj) {
                    float wv = swt[di * 5 + dj];
                    a10 = fmaf(rv[dj],     wv, a10);
                    a11 = fmaf(rv[dj + 1], wv, a11);
                }
            }
        }
    }

    // Inverse Haar: levels 2 -> 1 -> 0 (all values from smem)
    float u0 = st0[0][bi2][bj2], u1 = st0[1][bi2][bj2];
    float u2 = st0[2][bi2][bj2], u3 = st0[3][bi2][bj2];
    int r1 = bi2 >> 1, c1 = bj2 >> 1;
    float v0 = st1[0][r1][c1], v1 = st1[1][r1][c1];
    float v2 = st1[2][r1][c1], v3 = st1[3][r1][c1];
    int r2 = bi2 >> 2, c2 = bj2 >> 2;
    float w0 = st2[0][r2][c2], w1 = st2[1][r2][c2];
    float w2 = st2[2][r2][c2], w3 = st2[3][r2][c2];

    float sA = (r1 & 1) ? -1.f : 1.f;
    float sB = (c1 & 1) ? -1.f : 1.f;
    float nll2 = 0.5f * (w0 + sA * w1 + sB * w2 + sA * sB * w3);

    float sC = (bi2 & 1) ? -1.f : 1.f;
    float sD = (bj2 & 1) ? -1.f : 1.f;
    float nll1 = 0.5f * ((v0 + nll2) + sC * v1 + sD * v2 + sC * sD * v3);

    float y0 = u0 + nll1;
    float r00 = 0.5f * (y0 + u1 + u2 + u3);
    float r01 = 0.5f * (y0 + u1 - u2 - u3);
    float r10 = 0.5f * (y0 - u1 + u2 - u3);
    float r11 = 0.5f * (y0 - u1 - u2 + u3);

    float bsc = __ldg(base_scale + c);
    float bbv = __ldg(base_b + c);

    float* op = out + (size_t)(b * Cn + c) * 65536
                    + (size_t)(p0 + 2 * bi2) * 256 + (q0 + 2 * bj2);
    *(float2*)op         = make_float2(bsc * (a00 + bbv) + r00, bsc * (a01 + bbv) + r01);
    *(float2*)(op + 256) = make_float2(bsc * (a10 + bbv) + r10, bsc * (a11 + bbv) + r11);
}

// ---------------------------------------------------------------------------
// kernel_launch: 4 launches, one stream, graph-capturable, allocation-free.
// Input order: x, wt_filter, iwt_filter, base_w, base_b, base_scale,
//              wconv_w, wscale  (Haar filters are fixed constants, inlined)
// ---------------------------------------------------------------------------
extern "C" void kernel_launch(void* const* d_in, const int* in_sizes, int n_in,
                              void* d_out, int out_size) {
    (void)in_sizes; (void)n_in; (void)out_size;
    const float* x          = (const float*)d_in[0];
    const float* base_w     = (const float*)d_in[3];
    const float* base_b     = (const float*)d_in[4];
    const float* base_scale = (const float*)d_in[5];
    const float* wconv_w    = (const float*)d_in[6];
    const float* wscale     = (const float*)d_in[7];
    float* out = (float*)d_out;

    ll_kernel<<<dim3(4, Cn, Bn), 256>>>(x);
    fwd_kernel<1><<<dim3(4, Cn, Bn), 256>>>(wconv_w, wscale);
    fwd_kernel<2><<<dim3(1, Cn, Bn), 256>>>(wconv_w, wscale);
    final_kernel<<<dim3(64, Cn, Bn), 256>>>(x, base_w, base_b, base_scale,
                                            wconv_w, wscale, out);
}

// round 16
// speedup vs baseline: 1.0015x; 1.0005x over previous
#include <cuda_runtime.h>

// Problem constants (fixed by the reference): B=8, C=128, H=W=256, L=3, K=5
#define Bn 8
#define Cn 128

// Scratch (static device globals — no allocation in kernel_launch)
__device__ float g_tag1[(size_t)Bn * Cn * 4 * 64 * 64];   // 67 MB
__device__ float g_tag2[(size_t)Bn * Cn * 4 * 32 * 32];   // 17 MB
__device__ float g_ll1[(size_t)Bn * Cn * 128 * 128];      // 67 MB
__device__ float g_ll2[(size_t)Bn * Cn * 64 * 64];        // 17 MB

// ---------------------------------------------------------------------------
// ll_kernel: compute ll1 = HaarLL(x) and ll2 = HaarLL(ll1) in one streaming
// pass. Register-only, no smem, no syncs. Each thread: 8x8 x -> 4x4 ll1 -> 2x2 ll2.
// Block = 256 threads covers 128x128 of x; 4 blocks per (b,c) plane.
// ---------------------------------------------------------------------------
__global__ __launch_bounds__(256) void ll_kernel(const float* __restrict__ x)
{
    const int tid = threadIdx.x;
    const int tile = blockIdx.x;                 // 0..3
    const int c = blockIdx.y, b = blockIdx.z;
    const int ti = (tile >> 1) * 128, tj = (tile & 1) * 128;
    const int tyy = tid >> 4, txx = tid & 15;
    const int xi = ti + 8 * tyy, xj = tj + 8 * txx;

    const float* xp = x + (size_t)(b * Cn + c) * 65536;
    float* l1 = g_ll1 + (size_t)(b * Cn + c) * 16384;
    float* l2 = g_ll2 + (size_t)(b * Cn + c) * 4096;

    float l1v[4][4];
#pragma unroll
    for (int r = 0; r < 4; ++r) {
        const float* r0 = xp + (size_t)(xi + 2 * r) * 256 + xj;
        const float* r1 = r0 + 256;
        float4 a0 = *(const float4*)r0;
        float4 a1 = *(const float4*)(r0 + 4);
        float4 b0 = *(const float4*)r1;
        float4 b1 = *(const float4*)(r1 + 4);
        l1v[r][0] = 0.5f * (a0.x + a0.y + b0.x + b0.y);
        l1v[r][1] = 0.5f * (a0.z + a0.w + b0.z + b0.w);
        l1v[r][2] = 0.5f * (a1.x + a1.y + b1.x + b1.y);
        l1v[r][3] = 0.5f * (a1.z + a1.w + b1.z + b1.w);
        *(float4*)(l1 + (size_t)(xi / 2 + r) * 128 + xj / 2) =
            make_float4(l1v[r][0], l1v[r][1], l1v[r][2], l1v[r][3]);
    }
#pragma unroll
    for (int r = 0; r < 2; ++r) {
        float2 v = make_float2(
            0.5f * (l1v[2 * r][0] + l1v[2 * r][1] + l1v[2 * r + 1][0] + l1v[2 * r + 1][1]),
            0.5f * (l1v[2 * r][2] + l1v[2 * r][3] + l1v[2 * r + 1][2] + l1v[2 * r + 1][3]));
        *(float2*)(l2 + (size_t)(xi / 4 + r) * 64 + xj / 4) = v;
    }
}

// ---------------------------------------------------------------------------
// Forward kernel for levels 1 and 2: Haar analysis of ll{1,2} + depthwise 5x5
// conv (SAME, x wscale) -> tag{1,2}. No LL write (ll_kernel produced both).
// ---------------------------------------------------------------------------
template <int LEVEL>
__global__ __launch_bounds__(256) void fwd_kernel(
    const float* __restrict__ wconv_all,    // (L, 4C, 1, 5, 5)
    const float* __restrict__ wscale_all)   // (L, 1, 4C, 1, 1)
{
    constexpr int HC = (LEVEL == 1) ? 64 : 32;

    __shared__ __align__(16) float sc[4][36][40];
    __shared__ float sw[4][25];
    __shared__ float ss[4];

    const int tid = threadIdx.x;
    const int TPR = HC / 32;
    const int tx = blockIdx.x % TPR, ty = blockIdx.x / TPR;
    const int i0 = ty * 32, j0 = tx * 32;
    const int c = blockIdx.y, b = blockIdx.z;

    const float* wconv  = wconv_all  + (size_t)LEVEL * (4 * Cn) * 25;
    const float* wscale = wscale_all + (size_t)LEVEL * (4 * Cn);

    if (tid < 100) sw[tid / 25][tid % 25] = wconv[(c * 4 + tid / 25) * 25 + tid % 25];
    else if (tid < 104) ss[tid - 100] = wscale[c * 4 + (tid - 100)];

    const float* inp = (LEVEL == 1)
        ? (g_ll1 + (size_t)(b * Cn + c) * (4 * HC * HC))
        : (g_ll2 + (size_t)(b * Cn + c) * (4 * HC * HC));
    float* tag = (LEVEL == 1) ? g_tag1 : g_tag2;

    for (int idx = tid; idx < 36 * 36; idx += 256) {
        int ci = idx / 36, cj = idx % 36;
        int gi = i0 - 2 + ci, gj = j0 - 2 + cj;
        float x00 = 0.f, x01 = 0.f, x10 = 0.f, x11 = 0.f;
        if ((unsigned)gi < (unsigned)HC && (unsigned)gj < (unsigned)HC) {
            const float* p = inp + (size_t)(2 * gi) * (2 * HC) + 2 * gj;
            float2 a  = *(const float2*)p;
            float2 bb = *(const float2*)(p + 2 * HC);
            x00 = a.x; x01 = a.y; x10 = bb.x; x11 = bb.y;
        }
        float pa = x00 + x01, pb = x10 + x11;
        float pc = x00 - x01, pd = x10 - x11;
        sc[0][ci][cj] = 0.5f * (pa + pb);
        sc[1][ci][cj] = 0.5f * (pa - pb);
        sc[2][ci][cj] = 0.5f * (pc + pd);
        sc[3][ci][cj] = 0.5f * (pc - pd);
    }
    __syncthreads();

    const int f = tid >> 6;
    const int u = tid & 63;
    const int bi = u >> 3, bj = u & 7;

    float wreg[25];
#pragma unroll
    for (int k = 0; k < 25; ++k) wreg[k] = sw[f][k];

    float acc[4][4];
#pragma unroll
    for (int a = 0; a < 4; ++a)
#pragma unroll
        for (int d = 0; d < 4; ++d) acc[a][d] = 0.f;

#pragma unroll
    for (int r = 0; r < 8; ++r) {
        float rv[8];
        float4 v0 = *(const float4*)&sc[f][4 * bi + r][4 * bj];
        float4 v1 = *(const float4*)&sc[f][4 * bi + r][4 * bj + 4];
        rv[0] = v0.x; rv[1] = v0.y; rv[2] = v0.z; rv[3] = v0.w;
        rv[4] = v1.x; rv[5] = v1.y; rv[6] = v1.z; rv[7] = v1.w;
#pragma unroll
        for (int di = 0; di < 5; ++di) {
            int oi = r - di;
            if (oi >= 0 && oi < 4) {
#pragma unroll
                for (int dj = 0; dj < 5; ++dj) {
                    float wv = wreg[di * 5 + dj];
#pragma unroll
                    for (int cj = 0; cj < 4; ++cj)
                        acc[oi][cj] = fmaf(rv[cj + dj], wv, acc[oi][cj]);
                }
            }
        }
    }

    float s = ss[f];
    float* tp = tag + ((size_t)((b * Cn + c) * 4 + f)) * HC * HC;
#pragma unroll
    for (int oi = 0; oi < 4; ++oi) {
        float4 v = make_float4(acc[oi][0] * s, acc[oi][1] * s,
                               acc[oi][2] * s, acc[oi][3] * s);
        *(float4*)&tp[(size_t)(i0 + 4 * bi + oi) * HC + (j0 + 4 * bj)] = v;
    }
}

// ---------------------------------------------------------------------------
// final_kernel: per 32x32 output tile —
//   - load 40x40 x tile (float4, all-or-nothing bounds)
//   - stage tag1 (8x8x4) and tag2 (4x4x4) into smem (coalesced)
//   - compute level-0 Haar coefficients (20x20x4) in smem
//   - depthwise 5x5 conv -> tag0 (16x16x4) in smem  [tag0 never hits DRAM]
//   - base 5x5 conv on x + fused 3-level inverse Haar -> out
// ---------------------------------------------------------------------------
__global__ __launch_bounds__(256) void final_kernel(
    const float* __restrict__ x,
    const float* __restrict__ base_w,      // (C,1,5,5)
    const float* __restrict__ base_b,      // (C,)
    const float* __restrict__ base_scale,  // (1,C,1,1)
    const float* __restrict__ wconv_all,   // (L,4C,1,5,5): level 0 at offset 0
    const float* __restrict__ wscale_all,  // (L,1,4C,1,1)
    float* __restrict__ out)
{
    __shared__ __align__(16) float sx[40][40];
    __shared__ __align__(16) float scf[4][20][24];
    __shared__ __align__(16) float st0[4][16][20];
    __shared__ float st1[4][8][9];
    __shared__ float st2[4][4][5];
    __shared__ float swt[25];
    __shared__ float sw0[4][25];
    __shared__ float ss0[4];

    const int tid = threadIdx.x;
    const int tx = blockIdx.x & 7, ty = blockIdx.x >> 3;
    const int p0 = ty * 32, q0 = tx * 32;
    const int c = blockIdx.y, b = blockIdx.z;

    // Stage weights
    if (tid < 25) {
        swt[tid] = base_w[c * 25 + tid];
    } else if (tid >= 32 && tid < 132) {
        int k = tid - 32;
        sw0[k / 25][k % 25] = wconv_all[(c * 4 + k / 25) * 25 + k % 25];
    } else if (tid >= 160 && tid < 164) {
        ss0[tid - 160] = wscale_all[c * 4 + (tid - 160)];
    }

    // Stage tag1 / tag2 (cooperative, coalesced)
    const size_t bcc = (size_t)(b * Cn + c) * 4;
    const float* t1 = g_tag1 + bcc * 4096;
    const float* t2 = g_tag2 + bcc * 1024;
    const int I1 = p0 >> 2, J1 = q0 >> 2;
    const int I2 = p0 >> 3, J2 = q0 >> 3;
    {
        int f = tid >> 6, r = (tid >> 3) & 7, co = tid & 7;
        st1[f][r][co] = __ldg(t1 + f * 4096 + (I1 + r) * 64 + (J1 + co));
    }
    if (tid < 64) {
        int f = tid >> 4, r = (tid >> 2) & 3, co = tid & 3;
        st2[f][r][co] = __ldg(t2 + f * 1024 + (I2 + r) * 32 + (J2 + co));
    }

    // Stage x tile: rows/cols [p0-4, p0+35] x [q0-4, q0+35], float4 granules.
    // Each float4 is fully in-bounds or fully out (q0-4 ≡ 4 mod 8, granule aligned).
    const float* xp = x + (size_t)(b * Cn + c) * 65536;
    for (int idx = tid; idx < 400; idx += 256) {
        int r = idx / 10, c4 = idx % 10;
        int gi = p0 - 4 + r;
        int gj = q0 - 4 + 4 * c4;
        float4 v = make_float4(0.f, 0.f, 0.f, 0.f);
        if ((unsigned)gi < 256u && (unsigned)gj < 256u)
            v = *(const float4*)(xp + (size_t)gi * 256 + gj);
        *(float4*)&sx[r][4 * c4] = v;
    }
    __syncthreads();

    // Level-0 Haar coefficients (20x20 per subband, conv halo 2 included;
    // out-of-image coefficients are exactly 0 because sx halo is 0)
    for (int idx = tid; idx < 400; idx += 256) {
        int ci = idx / 20, cj = idx % 20;
        float2 a  = *(const float2*)&sx[2 * ci][2 * cj];
        float2 bb = *(const float2*)&sx[2 * ci + 1][2 * cj];
        float pa = a.x + a.y, pb = bb.x + bb.y;
        float pc = a.x - a.y, pd = bb.x - bb.y;
        scf[0][ci][cj] = 0.5f * (pa + pb);
        scf[1][ci][cj] = 0.5f * (pa - pb);
        scf[2][ci][cj] = 0.5f * (pc + pd);
        scf[3][ci][cj] = 0.5f * (pc - pd);
    }
    __syncthreads();

    // tag0 = wscale0 * dwconv5x5(coeffs): subband f handled by warp-group f,
    // each thread 1x4 outputs (row bi, cols 4*(u&3) ..)
    {
        int f = tid >> 6, u = tid & 63;
        int bi = u >> 2, bj4 = (u & 3) * 4;
        float wr[25];
#pragma unroll
        for (int k = 0; k < 25; ++k) wr[k] = sw0[f][k];
        float a0 = 0.f, a1 = 0.f, a2 = 0.f, a3 = 0.f;
#pragma unroll
        for (int di = 0; di < 5; ++di) {
            float rv[8];
            float4 v0 = *(const float4*)&scf[f][bi + di][bj4];
            float4 v1 = *(const float4*)&scf[f][bi + di][bj4 + 4];
            rv[0] = v0.x; rv[1] = v0.y; rv[2] = v0.z; rv[3] = v0.w;
            rv[4] = v1.x; rv[5] = v1.y; rv[6] = v1.z; rv[7] = v1.w;
#pragma unroll
            for (int dj = 0; dj < 5; ++dj) {
                float wv = wr[di * 5 + dj];
                a0 = fmaf(rv[dj],     wv, a0);
                a1 = fmaf(rv[dj + 1], wv, a1);
                a2 = fmaf(rv[dj + 2], wv, a2);
                a3 = fmaf(rv[dj + 3], wv, a3);
            }
        }
        float s = ss0[f];
        *(float4*)&st0[f][bi][bj4] = make_float4(a0 * s, a1 * s, a2 * s, a3 * s);
    }
    __syncthreads();

    // Final phase: base 5x5 conv (2x2 outputs) + fused 3-level inverse Haar
    const int bi2 = tid >> 4, bj2 = tid & 15;

    float a00 = 0.f, a01 = 0.f, a10 = 0.f, a11 = 0.f;
#pragma unroll
    for (int r = 0; r < 7; ++r) {
        float rv[8];
        const float* rowp = &sx[2 * bi2 + 2 + r][2 * bj2 + 2];
#pragma unroll
        for (int k = 0; k < 4; ++k) {
            float2 t = *(const float2*)(rowp + 2 * k);
            rv[2 * k] = t.x; rv[2 * k + 1] = t.y;
        }
        {
            int di = r;           // oi = 0
            if (di < 5) {
#pragma unroll
                for (int dj = 0; dj < 5; ++dj) {
                    float wv = swt[di * 5 + dj];
                    a00 = fmaf(rv[dj],     wv, a00);
                    a01 = fmaf(rv[dj + 1], wv, a01);
                }
            }
        }
        {
            int di = r - 1;       // oi = 1
            if (di >= 0 && di < 5) {
#pragma unroll
                for (int dj = 0; dj < 5; ++dj) {
                    float wv = swt[di * 5 + dj];
                    a10 = fmaf(rv[dj],     wv, a10);
                    a11 = fmaf(rv[dj + 1], wv, a11);
                }
            }
        }
    }

    // Inverse Haar: levels 2 -> 1 -> 0 (all values from smem)
    float u0 = st0[0][bi2][bj2], u1 = st0[1][bi2][bj2];
    float u2 = st0[2][bi2][bj2], u3 = st0[3][bi2][bj2];
    int r1 = bi2 >> 1, c1 = bj2 >> 1;
    float v0 = st1[0][r1][c1], v1 = st1[1][r1][c1];
    float v2 = st1[2][r1][c1], v3 = st1[3][r1][c1];
    int r2 = bi2 >> 2, c2 = bj2 >> 2;
    float w0 = st2[0][r2][c2], w1 = st2[1][r2][c2];
    float w2 = st2[2][r2][c2], w3 = st2[3][r2][c2];

    float sA = (r1 & 1) ? -1.f : 1.f;
    float sB = (c1 & 1) ? -1.f : 1.f;
    float nll2 = 0.5f * (w0 + sA * w1 + sB * w2 + sA * sB * w3);

    float sC = (bi2 & 1) ? -1.f : 1.f;
    float sD = (bj2 & 1) ? -1.f : 1.f;
    float nll1 = 0.5f * ((v0 + nll2) + sC * v1 + sD * v2 + sC * sD * v3);

    float y0 = u0 + nll1;
    float r00 = 0.5f * (y0 + u1 + u2 + u3);
    float r01 = 0.5f * (y0 + u1 - u2 - u3);
    float r10 = 0.5f * (y0 - u1 + u2 - u3);
    float r11 = 0.5f * (y0 - u1 - u2 + u3);

    float bsc = __ldg(base_scale + c);
    float bbv = __ldg(base_b + c);

    float* op = out + (size_t)(b * Cn + c) * 65536
                    + (size_t)(p0 + 2 * bi2) * 256 + (q0 + 2 * bj2);
    *(float2*)op         = make_float2(bsc * (a00 + bbv) + r00, bsc * (a01 + bbv) + r01);
    *(float2*)(op + 256) = make_float2(bsc * (a10 + bbv) + r10, bsc * (a11 + bbv) + r11);
}

// ---------------------------------------------------------------------------
// kernel_launch: 4 launches, one stream, graph-capturable, allocation-free.
// Input order: x, wt_filter, iwt_filter, base_w, base_b, base_scale,
//              wconv_w, wscale  (Haar filters are fixed constants, inlined)
// ---------------------------------------------------------------------------
extern "C" void kernel_launch(void* const* d_in, const int* in_sizes, int n_in,
                              void* d_out, int out_size) {
    (void)in_sizes; (void)n_in; (void)out_size;
    const float* x          = (const float*)d_in[0];
    const float* base_w     = (const float*)d_in[3];
    const float* base_b     = (const float*)d_in[4];
    const float* base_scale = (const float*)d_in[5];
    const float* wconv_w    = (const float*)d_in[6];
    const float* wscale     = (const float*)d_in[7];
    float* out = (float*)d_out;

    ll_kernel<<<dim3(4, Cn, Bn), 256>>>(x);
    fwd_kernel<1><<<dim3(4, Cn, Bn), 256>>>(wconv_w, wscale);
    fwd_kernel<2><<<dim3(1, Cn, Bn), 256>>>(wconv_w, wscale);
    final_kernel<<<dim3(64, Cn, Bn), 256>>>(x, base_w, base_b, base_scale,
                                            wconv_w, wscale, out);
}

// round 17
// speedup vs baseline: 1.1438x; 1.1420x over previous
#include <cuda_runtime.h>

// Problem constants (fixed by the reference): B=8, C=128, H=W=256, L=3, K=5
#define Bn 8
#define Cn 128

// Scratch (static device globals — no allocation in kernel_launch)
__device__ float g_tag1[(size_t)Bn * Cn * 4 * 64 * 64];   // 67 MB
__device__ float g_tag2[(size_t)Bn * Cn * 4 * 32 * 32];   // 17 MB
__device__ float g_ll1[(size_t)Bn * Cn * 128 * 128];      // 67 MB
__device__ float g_ll2[(size_t)Bn * Cn * 64 * 64];        // 17 MB

// ---------------------------------------------------------------------------
// ll_kernel: ll1 = HaarLL(x) and ll2 = HaarLL(ll1) in one streaming pass.
// ---------------------------------------------------------------------------
__global__ __launch_bounds__(256) void ll_kernel(const float* __restrict__ x)
{
    const int tid = threadIdx.x;
    const int tile = blockIdx.x;                 // 0..3
    const int c = blockIdx.y, b = blockIdx.z;
    const int ti = (tile >> 1) * 128, tj = (tile & 1) * 128;
    const int tyy = tid >> 4, txx = tid & 15;
    const int xi = ti + 8 * tyy, xj = tj + 8 * txx;

    const float* xp = x + (size_t)(b * Cn + c) * 65536;
    float* l1 = g_ll1 + (size_t)(b * Cn + c) * 16384;
    float* l2 = g_ll2 + (size_t)(b * Cn + c) * 4096;

    float l1v[4][4];
#pragma unroll
    for (int r = 0; r < 4; ++r) {
        const float* r0 = xp + (size_t)(xi + 2 * r) * 256 + xj;
        const float* r1 = r0 + 256;
        float4 a0 = *(const float4*)r0;
        float4 a1 = *(const float4*)(r0 + 4);
        float4 b0 = *(const float4*)r1;
        float4 b1 = *(const float4*)(r1 + 4);
        l1v[r][0] = 0.5f * (a0.x + a0.y + b0.x + b0.y);
        l1v[r][1] = 0.5f * (a0.z + a0.w + b0.z + b0.w);
        l1v[r][2] = 0.5f * (a1.x + a1.y + b1.x + b1.y);
        l1v[r][3] = 0.5f * (a1.z + a1.w + b1.z + b1.w);
        *(float4*)(l1 + (size_t)(xi / 2 + r) * 128 + xj / 2) =
            make_float4(l1v[r][0], l1v[r][1], l1v[r][2], l1v[r][3]);
    }
#pragma unroll
    for (int r = 0; r < 2; ++r) {
        float2 v = make_float2(
            0.5f * (l1v[2 * r][0] + l1v[2 * r][1] + l1v[2 * r + 1][0] + l1v[2 * r + 1][1]),
            0.5f * (l1v[2 * r][2] + l1v[2 * r][3] + l1v[2 * r + 1][2] + l1v[2 * r + 1][3]));
        *(float2*)(l2 + (size_t)(xi / 4 + r) * 64 + xj / 4) = v;
    }
}

// ---------------------------------------------------------------------------
// fwd_kernel for levels 1 & 2: Haar analysis of ll{1,2} + depthwise 5x5 conv
// ---------------------------------------------------------------------------
template <int LEVEL>
__global__ __launch_bounds__(256) void fwd_kernel(
    const float* __restrict__ wconv_all,
    const float* __restrict__ wscale_all)
{
    constexpr int HC = (LEVEL == 1) ? 64 : 32;

    __shared__ __align__(16) float sc[4][36][40];
    __shared__ float sw[4][25];
    __shared__ float ss[4];

    const int tid = threadIdx.x;
    const int TPR = HC / 32;
    const int tx = blockIdx.x % TPR, ty = blockIdx.x / TPR;
    const int i0 = ty * 32, j0 = tx * 32;
    const int c = blockIdx.y, b = blockIdx.z;

    const float* wconv  = wconv_all  + (size_t)LEVEL * (4 * Cn) * 25;
    const float* wscale = wscale_all + (size_t)LEVEL * (4 * Cn);

    if (tid < 100) sw[tid / 25][tid % 25] = wconv[(c * 4 + tid / 25) * 25 + tid % 25];
    else if (tid < 104) ss[tid - 100] = wscale[c * 4 + (tid - 100)];

    const float* inp = (LEVEL == 1)
        ? (g_ll1 + (size_t)(b * Cn + c) * (4 * HC * HC))
        : (g_ll2 + (size_t)(b * Cn + c) * (4 * HC * HC));
    float* tag = (LEVEL == 1) ? g_tag1 : g_tag2;

    for (int idx = tid; idx < 36 * 36; idx += 256) {
        int ci = idx / 36, cj = idx % 36;
        int gi = i0 - 2 + ci, gj = j0 - 2 + cj;
        float x00 = 0.f, x01 = 0.f, x10 = 0.f, x11 = 0.f;
        if ((unsigned)gi < (unsigned)HC && (unsigned)gj < (unsigned)HC) {
            const float* p = inp + (size_t)(2 * gi) * (2 * HC) + 2 * gj;
            float2 a  = *(const float2*)p;
            float2 bb = *(const float2*)(p + 2 * HC);
            x00 = a.x; x01 = a.y; x10 = bb.x; x11 = bb.y;
        }
        float pa = x00 + x01, pb = x10 + x11;
        float pc = x00 - x01, pd = x10 - x11;
        sc[0][ci][cj] = 0.5f * (pa + pb);
        sc[1][ci][cj] = 0.5f * (pa - pb);
        sc[2][ci][cj] = 0.5f * (pc + pd);
        sc[3][ci][cj] = 0.5f * (pc - pd);
    }
    __syncthreads();

    const int f = tid >> 6;
    const int u = tid & 63;
    const int bi = u >> 3, bj = u & 7;

    float wreg[25];
#pragma unroll
    for (int k = 0; k < 25; ++k) wreg[k] = sw[f][k];

    float acc[4][4];
#pragma unroll
    for (int a = 0; a < 4; ++a)
#pragma unroll
        for (int d = 0; d < 4; ++d) acc[a][d] = 0.f;

#pragma unroll
    for (int r = 0; r < 8; ++r) {
        float rv[8];
        float4 v0 = *(const float4*)&sc[f][4 * bi + r][4 * bj];
        float4 v1 = *(const float4*)&sc[f][4 * bi + r][4 * bj + 4];
        rv[0] = v0.x; rv[1] = v0.y; rv[2] = v0.z; rv[3] = v0.w;
        rv[4] = v1.x; rv[5] = v1.y; rv[6] = v1.z; rv[7] = v1.w;
#pragma unroll
        for (int di = 0; di < 5; ++di) {
            int oi = r - di;
            if (oi >= 0 && oi < 4) {
#pragma unroll
                for (int dj = 0; dj < 5; ++dj) {
                    float wv = wreg[di * 5 + dj];
#pragma unroll
                    for (int cj = 0; cj < 4; ++cj)
                        acc[oi][cj] = fmaf(rv[cj + dj], wv, acc[oi][cj]);
                }
            }
        }
    }

    float s = ss[f];
    float* tp = tag + ((size_t)((b * Cn + c) * 4 + f)) * HC * HC;
#pragma unroll
    for (int oi = 0; oi < 4; ++oi) {
        float4 v = make_float4(acc[oi][0] * s, acc[oi][1] * s,
                               acc[oi][2] * s, acc[oi][3] * s);
        *(float4*)&tp[(size_t)(i0 + 4 * bi + oi) * HC + (j0 + 4 * bj)] = v;
    }
}

// ---------------------------------------------------------------------------
// final_kernel (warp-specialized):
//   group A (tid<128): scf (level-0 Haar coeffs, float4 in/out) -> bar.sync(1)
//                      -> tag0 5x5 conv (1 warp/subband, 2x4 blocking) -> st0
//   group B (tid>=128): base 5x5 conv (2x4 blocking, aligned LDS.128), accs
//                       kept in registers across the join; after __syncthreads
//                       does inverse-Haar + output writes (float4 stores)
// ---------------------------------------------------------------------------
__global__ __launch_bounds__(256) void final_kernel(
    const float* __restrict__ x,
    const float* __restrict__ base_w,      // (C,1,5,5)
    const float* __restrict__ base_b,      // (C,)
    const float* __restrict__ base_scale,  // (1,C,1,1)
    const float* __restrict__ wconv_all,   // (L,4C,1,5,5): level 0 at offset 0
    const float* __restrict__ wscale_all,  // (L,1,4C,1,1)
    float* __restrict__ out)
{
    __shared__ __align__(16) float sx[40][40];
    __shared__ __align__(16) float scf[4][20][20];
    __shared__ __align__(16) float st0[4][16][20];
    __shared__ float st1[4][8][9];
    __shared__ float st2[4][4][5];
    __shared__ float swt[25];
    __shared__ float sw0[4][25];
    __shared__ float ss0[4];

    const int tid = threadIdx.x;
    const int tx = blockIdx.x & 7, ty = blockIdx.x >> 3;
    const int p0 = ty * 32, q0 = tx * 32;
    const int c = blockIdx.y, b = blockIdx.z;

    // Stage weights
    if (tid < 25) {
        swt[tid] = base_w[c * 25 + tid];
    } else if (tid >= 32 && tid < 132) {
        int k = tid - 32;
        sw0[k / 25][k % 25] = wconv_all[(c * 4 + k / 25) * 25 + k % 25];
    } else if (tid >= 160 && tid < 164) {
        ss0[tid - 160] = wscale_all[c * 4 + (tid - 160)];
    }

    // Stage tag1 / tag2 (coalesced)
    const size_t bcc = (size_t)(b * Cn + c) * 4;
    const float* t1g = g_tag1 + bcc * 4096;
    const float* t2g = g_tag2 + bcc * 1024;
    const int I1 = p0 >> 2, J1 = q0 >> 2;
    const int I2 = p0 >> 3, J2 = q0 >> 3;
    {
        int f = tid >> 6, r = (tid >> 3) & 7, co = tid & 7;
        st1[f][r][co] = __ldg(t1g + f * 4096 + (I1 + r) * 64 + (J1 + co));
    }
    if (tid < 64) {
        int f = tid >> 4, r = (tid >> 2) & 3, co = tid & 3;
        st2[f][r][co] = __ldg(t2g + f * 1024 + (I2 + r) * 32 + (J2 + co));
    }

    // Stage x tile: rows/cols [p0-4, p0+35] x [q0-4, q0+35], float4 granules
    const float* xp = x + (size_t)(b * Cn + c) * 65536;
    for (int idx = tid; idx < 400; idx += 256) {
        int r = idx / 10, c4 = idx % 10;
        int gi = p0 - 4 + r;
        int gj = q0 - 4 + 4 * c4;
        float4 v = make_float4(0.f, 0.f, 0.f, 0.f);
        if ((unsigned)gi < 256u && (unsigned)gj < 256u)
            v = *(const float4*)(xp + (size_t)gi * 256 + gj);
        *(float4*)&sx[r][4 * c4] = v;
    }
    __syncthreads();

    if (tid < 128) {
        // ================= GROUP A: scf + tag0 conv =================
        if (tid < 100) {
            int ci = tid / 5, cj4 = tid % 5;   // coeff row 0..19, col quad 0..4
            float4 a0 = *(const float4*)&sx[2 * ci][8 * cj4];
            float4 a1 = *(const float4*)&sx[2 * ci][8 * cj4 + 4];
            float4 b0 = *(const float4*)&sx[2 * ci + 1][8 * cj4];
            float4 b1 = *(const float4*)&sx[2 * ci + 1][8 * cj4 + 4];
            float xt[4][4] = {{a0.x, a0.y, b0.x, b0.y},
                              {a0.z, a0.w, b0.z, b0.w},
                              {a1.x, a1.y, b1.x, b1.y},
                              {a1.z, a1.w, b1.z, b1.w}};
            float s0[4], s1[4], s2[4], s3[4];
#pragma unroll
            for (int p = 0; p < 4; ++p) {
                float pa = xt[p][0] + xt[p][1], pb = xt[p][2] + xt[p][3];
                float pc = xt[p][0] - xt[p][1], pd = xt[p][2] - xt[p][3];
                s0[p] = 0.5f * (pa + pb);
                s1[p] = 0.5f * (pa - pb);
                s2[p] = 0.5f * (pc + pd);
                s3[p] = 0.5f * (pc - pd);
            }
            *(float4*)&scf[0][ci][4 * cj4] = make_float4(s0[0], s0[1], s0[2], s0[3]);
            *(float4*)&scf[1][ci][4 * cj4] = make_float4(s1[0], s1[1], s1[2], s1[3]);
            *(float4*)&scf[2][ci][4 * cj4] = make_float4(s2[0], s2[1], s2[2], s2[3]);
            *(float4*)&scf[3][ci][4 * cj4] = make_float4(s3[0], s3[1], s3[2], s3[3]);
        }
        asm volatile("bar.sync 1, 128;" ::: "memory");

        // tag0 conv: one warp per subband, 2x4 outputs per thread
        const int f  = tid >> 5;
        const int l  = tid & 31;
        const int rp = l >> 2, cg = l & 3;   // out rows 2rp..2rp+1, cols 4cg..4cg+3
        float acc0[4] = {0.f, 0.f, 0.f, 0.f};
        float acc1[4] = {0.f, 0.f, 0.f, 0.f};
        float wA[5], wB[5];
#pragma unroll
        for (int ir = 0; ir < 6; ++ir) {
            float rv[8];
            float4 v0 = *(const float4*)&scf[f][2 * rp + ir][4 * cg];
            float4 v1 = *(const float4*)&scf[f][2 * rp + ir][4 * cg + 4];
            rv[0] = v0.x; rv[1] = v0.y; rv[2] = v0.z; rv[3] = v0.w;
            rv[4] = v1.x; rv[5] = v1.y; rv[6] = v1.z; rv[7] = v1.w;
            if (ir < 5) {
#pragma unroll
                for (int k = 0; k < 5; ++k) wA[k] = sw0[f][ir * 5 + k];
#pragma unroll
                for (int dj = 0; dj < 5; ++dj)
#pragma unroll
                    for (int cc = 0; cc < 4; ++cc)
                        acc0[cc] = fmaf(rv[cc + dj], wA[dj], acc0[cc]);
            }
            if (ir >= 1) {
#pragma unroll
                for (int dj = 0; dj < 5; ++dj)
#pragma unroll
                    for (int cc = 0; cc < 4; ++cc)
                        acc1[cc] = fmaf(rv[cc + dj], wB[dj], acc1[cc]);
            }
#pragma unroll
            for (int k = 0; k < 5; ++k) wB[k] = wA[k];
        }
        float s = ss0[f];
        *(float4*)&st0[f][2 * rp][4 * cg] =
            make_float4(acc0[0] * s, acc0[1] * s, acc0[2] * s, acc0[3] * s);
        *(float4*)&st0[f][2 * rp + 1][4 * cg] =
            make_float4(acc1[0] * s, acc1[1] * s, acc1[2] * s, acc1[3] * s);

        __syncthreads();   // join; group A done
    } else {
        // ================= GROUP B: base conv, then writes =================
        const int u  = tid - 128;
        const int rp = u >> 3, cg = u & 7;   // out rows 2rp..2rp+1, cols 4cg..4cg+3
        float acc0[4] = {0.f, 0.f, 0.f, 0.f};
        float acc1[4] = {0.f, 0.f, 0.f, 0.f};
        float wA[5], wB[5];
#pragma unroll
        for (int ir = 0; ir < 6; ++ir) {
            // need sx cols 4cg+2 .. 4cg+9 -> aligned quads 4cg, 4cg+4, 4cg+8
            const float* rowp = &sx[2 * rp + 2 + ir][4 * cg];
            float4 A = *(const float4*)rowp;
            float4 Bq = *(const float4*)(rowp + 4);
            float4 Cq = *(const float4*)(rowp + 8);
            float rv[12] = {A.x, A.y, A.z, A.w, Bq.x, Bq.y, Bq.z, Bq.w,
                            Cq.x, Cq.y, Cq.z, Cq.w};
            if (ir < 5) {
#pragma unroll
                for (int k = 0; k < 5; ++k) wA[k] = swt[ir * 5 + k];
#pragma unroll
                for (int dj = 0; dj < 5; ++dj)
#pragma unroll
                    for (int cc = 0; cc < 4; ++cc)
                        acc0[cc] = fmaf(rv[2 + cc + dj], wA[dj], acc0[cc]);
            }
            if (ir >= 1) {
#pragma unroll
                for (int dj = 0; dj < 5; ++dj)
#pragma unroll
                    for (int cc = 0; cc < 4; ++cc)
                        acc1[cc] = fmaf(rv[2 + cc + dj], wB[dj], acc1[cc]);
            }
#pragma unroll
            for (int k = 0; k < 5; ++k) wB[k] = wA[k];
        }

        __syncthreads();   // wait for st0 from group A

        // inverse Haar + combine + write (2 quads: tag0 (rp,2cg), (rp,2cg+1))
        const int r1 = rp >> 1, c1 = cg;
        const int r2 = rp >> 2, c2 = cg >> 1;
        float v0 = st1[0][r1][c1], v1 = st1[1][r1][c1];
        float v2 = st1[2][r1][c1], v3 = st1[3][r1][c1];
        float w0 = st2[0][r2][c2], w1 = st2[1][r2][c2];
        float w2 = st2[2][r2][c2], w3 = st2[3][r2][c2];

        float sA = (r1 & 1) ? -1.f : 1.f;
        float sB = (c1 & 1) ? -1.f : 1.f;
        float nll2 = 0.5f * (w0 + sA * w1 + sB * w2 + sA * sB * w3);
        float sC = (rp & 1) ? -1.f : 1.f;

        float bsc = __ldg(base_scale + c);
        float bbv = __ldg(base_b + c);

        float o0[4], o1[4];
#pragma unroll
        for (int qq = 0; qq < 2; ++qq) {
            int j = 2 * cg + qq;
            float sD = qq ? -1.f : 1.f;
            float u0 = st0[0][rp][j], u1 = st0[1][rp][j];
            float u2 = st0[2][rp][j], u3 = st0[3][rp][j];
            float nll1 = 0.5f * ((v0 + nll2) + sC * v1 + sD * v2 + sC * sD * v3);
            float y0 = u0 + nll1;
            o0[2 * qq]     = bsc * (acc0[2 * qq]     + bbv) + 0.5f * (y0 + u1 + u2 + u3);
            o0[2 * qq + 1] = bsc * (acc0[2 * qq + 1] + bbv) + 0.5f * (y0 + u1 - u2 - u3);
            o1[2 * qq]     = bsc * (acc1[2 * qq]     + bbv) + 0.5f * (y0 - u1 + u2 - u3);
            o1[2 * qq + 1] = bsc * (acc1[2 * qq + 1] + bbv) + 0.5f * (y0 - u1 - u2 + u3);
        }

        float* op = out + (size_t)(b * Cn + c) * 65536
                        + (size_t)(p0 + 2 * rp) * 256 + (q0 + 4 * cg);
        *(float4*)op         = make_float4(o0[0], o0[1], o0[2], o0[3]);
        *(float4*)(op + 256) = make_float4(o1[0], o1[1], o1[2], o1[3]);
    }
}

// ---------------------------------------------------------------------------
// kernel_launch: 4 launches, one stream, graph-capturable, allocation-free.
// Input order: x, wt_filter, iwt_filter, base_w, base_b, base_scale,
//              wconv_w, wscale  (Haar filters are fixed constants, inlined)
// ---------------------------------------------------------------------------
extern "C" void kernel_launch(void* const* d_in, const int* in_sizes, int n_in,
                              void* d_out, int out_size) {
    (void)in_sizes; (void)n_in; (void)out_size;
    const float* x          = (const float*)d_in[0];
    const float* base_w     = (const float*)d_in[3];
    const float* base_b     = (const float*)d_in[4];
    const float* base_scale = (const float*)d_in[5];
    const float* wconv_w    = (const float*)d_in[6];
    const float* wscale     = (const float*)d_in[7];
    float* out = (float*)d_out;

    ll_kernel<<<dim3(4, Cn, Bn), 256>>>(x);
    fwd_kernel<1><<<dim3(4, Cn, Bn), 256>>>(wconv_w, wscale);
    fwd_kernel<2><<<dim3(1, Cn, Bn), 256>>>(wconv_w, wscale);
    final_kernel<<<dim3(64, Cn, Bn), 256>>>(x, base_w, base_b, base_scale,
                                            wconv_w, wscale, out);
}